// round 5
// baseline (speedup 1.0000x reference)
#include <cuda_runtime.h>
#include <math.h>

#define NUM_GRAPHS 16

constexpr int IN_F = 262;
constexpr int HID  = 128;
constexpr int H1   = 4;
constexpr int C1   = 512;     // H1*HID
constexpr int NMAX = 50000;
constexpr int EMAX = 400000;

// ---------------- scratch (device globals; no allocation allowed) -------------
__device__ float g_W1t[IN_F * C1];
__device__ float g_Wh1[(size_t)NMAX * C1];
__device__ float g_h1 [(size_t)NMAX * C1];
__device__ float g_Wh2[(size_t)NMAX * HID];
__device__ float g_h2t[(size_t)NMAX * HID];
__device__ float g_P  [(size_t)NMAX * HID];
__device__ float g_Q  [(size_t)NMAX * HID];
__device__ float g_es1[H1 * NMAX], g_ed1[H1 * NMAX];
__device__ float g_es2[NMAX],      g_ed2[NMAX];
__device__ int   g_src[EMAX], g_dst[EMAX];
__device__ int   g_batch[NMAX];
__device__ int   g_deg[NMAX];
__device__ int   g_rowstart[NMAX + 1];
__device__ int   g_pos[NMAX];
__device__ int   g_csr_src[EMAX];
__device__ int   g_csr_eid[EMAX];
__device__ float g_bnsum[C1], g_bnss[C1], g_scale[C1], g_shift[C1];
__device__ float g_pool[NUM_GRAPHS * HID];
__device__ float g_cnt[NUM_GRAPHS];
__device__ int   g_is64;

// ---------------- utility kernels --------------------------------------------
__global__ void zero_kernel(float* p, size_t n) {
    size_t i = (size_t)blockIdx.x * blockDim.x + threadIdx.x;
    if (i < n) p[i] = 0.f;
}

__global__ void copy_int_kernel(const int* a, int* b, int n) {
    int i = blockIdx.x * blockDim.x + threadIdx.x;
    if (i < n) b[i] = a[i];
}

// detect int64 vs int32 index buffers: for int64 little-endian nonneg values
// < 2^31, every odd 32-bit word is zero.
__global__ void detect_kernel(const unsigned* w, int nwords) {
    __shared__ unsigned acc;
    if (threadIdx.x == 0) acc = 0u;
    __syncthreads();
    unsigned v = 0;
    for (int i = 1 + 2 * threadIdx.x; i < nwords; i += 2 * blockDim.x) v |= w[i];
    atomicOr(&acc, v);
    __syncthreads();
    if (threadIdx.x == 0) g_is64 = (acc == 0u) ? 1 : 0;
}

__global__ void convert_idx_kernel(const void* p, int* src, int* dst, int E) {
    int i = blockIdx.x * blockDim.x + threadIdx.x;
    if (i >= 2 * E) return;
    int v = g_is64 ? (int)((const long long*)p)[i] : ((const int*)p)[i];
    if (i < E) src[i] = v; else dst[i - E] = v;
}

__global__ void convert_batch_kernel(const void* p, int* b, int N) {
    int i = blockIdx.x * blockDim.x + threadIdx.x;
    if (i >= N) return;
    b[i] = g_is64 ? (int)((const long long*)p)[i] : ((const int*)p)[i];
}

// ---------------- CSR build (by dst) ------------------------------------------
__global__ void count_deg_kernel(const int* dst, int* deg, int E) {
    int i = blockIdx.x * blockDim.x + threadIdx.x;
    if (i < E) atomicAdd(&deg[dst[i]], 1);
}

__global__ void scan_kernel(const int* deg, int* rowstart, int N) {
    __shared__ int ssum[1024];
    int t = threadIdx.x;
    int per = (N + 1023) / 1024;
    int a = t * per, b = min(N, a + per);
    int s = 0;
    for (int i = a; i < b; i++) s += deg[i];
    ssum[t] = s;
    __syncthreads();
    for (int off = 1; off < 1024; off <<= 1) {
        int v = (t >= off) ? ssum[t - off] : 0;
        __syncthreads();
        ssum[t] += v;
        __syncthreads();
    }
    int base = (t == 0) ? 0 : ssum[t - 1];
    for (int i = a; i < b; i++) { rowstart[i] = base; base += deg[i]; }
    if (t == 1023) rowstart[N] = base;
}

__global__ void fill_csr_kernel(const int* src, const int* dst, int* pos,
                                int* csr_src, int* csr_eid, int E) {
    int i = blockIdx.x * blockDim.x + threadIdx.x;
    if (i >= E) return;
    int p = atomicAdd(&pos[dst[i]], 1);
    csr_src[p] = src[i];
    csr_eid[p] = i;
}

// ---------------- W1 repack: (H,IN,HID) -> (IN, H*HID) ------------------------
__global__ void w1t_kernel(const float* __restrict__ W1, float* __restrict__ out) {
    int idx = blockIdx.x * blockDim.x + threadIdx.x;
    if (idx >= IN_F * C1) return;
    int i = idx >> 9;        // /512
    int c = idx & 511;
    int h = c >> 7;
    int o = c & 127;
    out[idx] = W1[((size_t)h * IN_F + i) * HID + o];
}

// ---------------- tiled fp32 SGEMM: C(MxN) = A(MxK) * B(KxN) ------------------
// N must be a multiple of 128 (true for all call sites: 512 / 128).
__global__ __launch_bounds__(256) void sgemm_kernel(
    const float* __restrict__ A, const float* __restrict__ B,
    float* __restrict__ C, int M, int N, int K) {
    __shared__ float As[8][128];
    __shared__ float Bs[8][128];
    const int tid = threadIdx.x;
    const int tx = tid & 15, ty = tid >> 4;
    const int row0 = blockIdx.x * 128, col0 = blockIdx.y * 128;
    float acc[8][8];
#pragma unroll
    for (int i = 0; i < 8; i++)
#pragma unroll
        for (int j = 0; j < 8; j++) acc[i][j] = 0.f;

    const int aRow = tid >> 1, aCol = (tid & 1) * 4;
    const int bRow = tid >> 5, bCol = (tid & 31) * 4;

    for (int k0 = 0; k0 < K; k0 += 8) {
        int m = row0 + aRow;
#pragma unroll
        for (int j = 0; j < 4; j++) {
            int k = k0 + aCol + j;
            As[aCol + j][aRow] = (m < M && k < K) ? A[(size_t)m * K + k] : 0.f;
        }
        int kb = k0 + bRow;
        if (kb < K) {
            const float* bp = &B[(size_t)kb * N + col0 + bCol];
            *(float4*)&Bs[bRow][bCol] = *(const float4*)bp;
        } else {
            *(float4*)&Bs[bRow][bCol] = make_float4(0.f, 0.f, 0.f, 0.f);
        }
        __syncthreads();
#pragma unroll
        for (int kk = 0; kk < 8; kk++) {
            float4 a0 = *(const float4*)&As[kk][ty * 8];
            float4 a1 = *(const float4*)&As[kk][ty * 8 + 4];
            float4 b0 = *(const float4*)&Bs[kk][tx * 8];
            float4 b1 = *(const float4*)&Bs[kk][tx * 8 + 4];
            float a[8] = {a0.x, a0.y, a0.z, a0.w, a1.x, a1.y, a1.z, a1.w};
            float b[8] = {b0.x, b0.y, b0.z, b0.w, b1.x, b1.y, b1.z, b1.w};
#pragma unroll
            for (int i = 0; i < 8; i++)
#pragma unroll
                for (int j = 0; j < 8; j++) acc[i][j] = fmaf(a[i], b[j], acc[i][j]);
        }
        __syncthreads();
    }
#pragma unroll
    for (int i = 0; i < 8; i++) {
        int m = row0 + ty * 8 + i;
        if (m >= M) continue;
        float* cp = &C[(size_t)m * N + col0 + tx * 8];
        *(float4*)cp       = make_float4(acc[i][0], acc[i][1], acc[i][2], acc[i][3]);
        *(float4*)(cp + 4) = make_float4(acc[i][4], acc[i][5], acc[i][6], acc[i][7]);
    }
}

// ---------------- per-node attention scores: es/ed ---------------------------
__global__ void node_scores_kernel(const float* __restrict__ Wh,
    const float* __restrict__ a_src, const float* __restrict__ a_dst,
    float* __restrict__ es, float* __restrict__ ed, int N, int H, int F) {
    int w = (blockIdx.x * blockDim.x + threadIdx.x) >> 5;
    int lane = threadIdx.x & 31;
    if (w >= N) return;
    const float* row = Wh + (size_t)w * H * F;
    for (int h = 0; h < H; h++) {
        float s = 0.f, d = 0.f;
        for (int o = lane; o < F; o += 32) {
            float v = row[h * F + o];
            s += v * a_src[h * F + o];
            d += v * a_dst[h * F + o];
        }
#pragma unroll
        for (int off = 16; off; off >>= 1) {
            s += __shfl_xor_sync(0xffffffffu, s, off);
            d += __shfl_xor_sync(0xffffffffu, d, off);
        }
        if (lane == 0) { es[h * N + w] = s; ed[h * N + w] = d; }
    }
}

// ---------------- fused edge-softmax + aggregation (one warp per dst,head) ----
// F must be 128.
__global__ void gat_aggregate_kernel(
    const int* __restrict__ rowstart, const int* __restrict__ csr_src,
    const int* __restrict__ csr_eid,
    const float* __restrict__ es, const float* __restrict__ ed,
    const float* __restrict__ Wh, float* __restrict__ out,
    float* __restrict__ attn_out, int N, int H, int F) {
    int w = (blockIdx.x * blockDim.x + threadIdx.x) >> 5;
    int lane = threadIdx.x & 31;
    if (w >= N * H) return;
    int n = w / H, h = w % H;
    int r0 = rowstart[n], r1 = rowstart[n + 1];
    float edv = ed[h * N + n];

    // pass 1: segment max, clamped at 0 (matches reference's maximum(seg_max,0))
    float m = 0.f;
    for (int i = r0 + lane; i < r1; i += 32) {
        float v = es[h * N + csr_src[i]] + edv;
        v = v > 0.f ? v : 0.2f * v;
        m = fmaxf(m, v);
    }
#pragma unroll
    for (int off = 16; off; off >>= 1) m = fmaxf(m, __shfl_xor_sync(~0u, m, off));

    // pass 2: sum of exp
    float ssum = 0.f;
    for (int i = r0 + lane; i < r1; i += 32) {
        float v = es[h * N + csr_src[i]] + edv;
        v = v > 0.f ? v : 0.2f * v;
        ssum += expf(v - m);
    }
#pragma unroll
    for (int off = 16; off; off >>= 1) ssum += __shfl_xor_sync(~0u, ssum, off);
    float inv = 1.f / (ssum + 1e-8f);

    // pass 3: weighted aggregation (lanes across F, serial over edges)
    float acc0 = 0.f, acc1 = 0.f, acc2 = 0.f, acc3 = 0.f;
    for (int i = r0; i < r1; i++) {
        int s = csr_src[i];
        float v = es[h * N + s] + edv;
        v = v > 0.f ? v : 0.2f * v;
        float a = expf(v - m) * inv;
        if (attn_out != nullptr && lane == 0) attn_out[csr_eid[i]] = a;
        const float* srow = Wh + (size_t)s * (H * F) + h * F;
        acc0 += a * srow[lane];
        acc1 += a * srow[lane + 32];
        acc2 += a * srow[lane + 64];
        acc3 += a * srow[lane + 96];
    }
    float* orow = out + (size_t)n * (H * F) + h * F;
    orow[lane]      = acc0;
    orow[lane + 32] = acc1;
    orow[lane + 64] = acc2;
    orow[lane + 96] = acc3;
}

// ---------------- elu + BN statistics ----------------------------------------
__global__ void elu_stats_kernel(const float* __restrict__ in, float* __restrict__ outp,
                                 float* sum, float* ss, int Nrows, int C) {
    int ch = threadIdx.x;   // blockDim.x == C
    float s = 0.f, q = 0.f;
    for (int r = blockIdx.x; r < Nrows; r += gridDim.x) {
        float v = in[(size_t)r * C + ch];
        v = v > 0.f ? v : expm1f(v);
        outp[(size_t)r * C + ch] = v;
        s += v; q += v * v;
    }
    atomicAdd(&sum[ch], s);
    atomicAdd(&ss[ch], q);
}

__global__ void bn_final_kernel(const float* sum, const float* ss,
                                const float* gam, const float* bet,
                                float* scale, float* shift, int C, float n) {
    int c = blockIdx.x * blockDim.x + threadIdx.x;
    if (c >= C) return;
    float mean = sum[c] / n;
    float var  = ss[c] / n - mean * mean;
    float r = rsqrtf(var + 1e-5f);
    float sc = gam[c] * r;
    scale[c] = sc;
    shift[c] = bet[c] - mean * sc;
}

__global__ void bn_apply_kernel(const float* __restrict__ in, float* __restrict__ out,
                                const float* __restrict__ scale,
                                const float* __restrict__ shift,
                                size_t total, int cmask) {
    size_t i = (size_t)blockIdx.x * blockDim.x + threadIdx.x;
    if (i >= total) return;
    int c = (int)(i & (size_t)cmask);
    out[i] = in[i] * scale[c] + shift[c];
}

// ---------------- global mean pool -------------------------------------------
__global__ void pool_kernel(const float* __restrict__ h2, const int* __restrict__ batch,
                            int N, float* pool, float* cnt) {
    __shared__ float sp[NUM_GRAPHS * HID];
    __shared__ float sc[NUM_GRAPHS];
    int t = threadIdx.x;   // 128
    for (int i = t; i < NUM_GRAPHS * HID; i += blockDim.x) sp[i] = 0.f;
    if (t < NUM_GRAPHS) sc[t] = 0.f;
    __syncthreads();
    int per = (N + gridDim.x - 1) / gridDim.x;
    int r0 = blockIdx.x * per, r1 = min(N, r0 + per);
    for (int r = r0; r < r1; r++) {
        int g = batch[r];
        sp[g * HID + t] += h2[(size_t)r * HID + t];
        if (t == 0) sc[g] += 1.f;
    }
    __syncthreads();
    for (int i = t; i < NUM_GRAPHS * HID; i += blockDim.x) atomicAdd(&pool[i], sp[i]);
    if (t < NUM_GRAPHS) atomicAdd(&cnt[t], sc[t]);
}

// ---------------- classifier head (tiny) --------------------------------------
__global__ void classifier_kernel(const float* pool, const float* cnt,
    const float* w1, const float* b1, const float* w2, const float* b2,
    float* logits) {
    __shared__ float gr[NUM_GRAPHS * HID];
    __shared__ float hid[NUM_GRAPHS * 64];
    int t = threadIdx.x;   // 1024
    for (int i = t; i < NUM_GRAPHS * HID; i += blockDim.x) {
        float c = cnt[i / HID];
        c = c < 1.f ? 1.f : c;
        gr[i] = pool[i] / c;
    }
    __syncthreads();
    if (t < NUM_GRAPHS * 64) {
        int g = t >> 6, j = t & 63;
        float s = b1[j];
        for (int k = 0; k < HID; k++) s += gr[g * HID + k] * w1[k * 64 + j];
        hid[t] = s > 0.f ? s : 0.f;
    }
    __syncthreads();
    if (t < NUM_GRAPHS * 2) {
        int g = t >> 1, c = t & 1;
        float s = b2[c];
        for (int k = 0; k < 64; k++) s += hid[g * 64 + k] * w2[k * 2 + c];
        logits[g * 2 + c] = s;
    }
}

// ---------------- edge importance head ----------------------------------------
__global__ void edge_imp_kernel(const int* __restrict__ src, const int* __restrict__ dst,
    const float* __restrict__ P, const float* __restrict__ Q,
    const float* __restrict__ b1, const float* __restrict__ w2,
    const float* __restrict__ b2, float* __restrict__ imp, int E) {
    int w = (blockIdx.x * blockDim.x + threadIdx.x) >> 5;
    int lane = threadIdx.x & 31;
    if (w >= E) return;
    int s = src[w], d = dst[w];
    const float* pr = P + (size_t)s * HID;
    const float* qr = Q + (size_t)d * HID;
    float acc = 0.f;
#pragma unroll
    for (int j = 0; j < 4; j++) {
        int o = lane + 32 * j;
        float v = pr[o] + qr[o] + b1[o];
        v = v > 0.f ? v : 0.f;
        acc += v * w2[o];
    }
#pragma unroll
    for (int off = 16; off; off >>= 1) acc += __shfl_xor_sync(~0u, acc, off);
    if (lane == 0) imp[w] = 1.f / (1.f + expf(-(acc + b2[0])));
}

// ---------------- launcher ----------------------------------------------------
extern "C" void kernel_launch(void* const* d_in, const int* in_sizes, int n_in,
                              void* d_out, int out_size) {
    const float* x      = (const float*)d_in[0];
    const void*  eidx   = d_in[1];
    const void*  batch  = d_in[2];
    const float* W1     = (const float*)d_in[3];
    const float* a_src1 = (const float*)d_in[4];
    const float* a_dst1 = (const float*)d_in[5];
    const float* W2     = (const float*)d_in[6];
    const float* a_src2 = (const float*)d_in[7];
    const float* a_dst2 = (const float*)d_in[8];
    const float* bn1_g  = (const float*)d_in[9];
    const float* bn1_b  = (const float*)d_in[10];
    const float* bn2_g  = (const float*)d_in[11];
    const float* bn2_b  = (const float*)d_in[12];
    const float* cls_w1 = (const float*)d_in[13];
    const float* cls_b1 = (const float*)d_in[14];
    const float* cls_w2 = (const float*)d_in[15];
    const float* cls_b2 = (const float*)d_in[16];
    const float* ep_w1  = (const float*)d_in[17];
    const float* ep_b1  = (const float*)d_in[18];
    const float* ep_w2  = (const float*)d_in[19];
    const float* ep_b2  = (const float*)d_in[20];

    const int N = in_sizes[0] / IN_F;
    const int E = in_sizes[1] / 2;

    float* out        = (float*)d_out;
    float* out_logits = out;
    float* out_h2     = out + NUM_GRAPHS * 2;
    float* out_imp    = out_h2 + (size_t)N * HID;
    float* out_attn   = out_imp + E;

    void* p;
    float *W1t, *Wh1, *h1, *Wh2, *h2t, *Pm, *Qm;
    float *es1, *ed1, *es2, *ed2, *bnsum, *bnss, *scale, *shift, *pool, *cnt;
    int *srcA, *dstA, *batchA, *deg, *rowstart, *pos, *csrs, *csre;
    cudaGetSymbolAddress(&p, g_W1t);      W1t  = (float*)p;
    cudaGetSymbolAddress(&p, g_Wh1);      Wh1  = (float*)p;
    cudaGetSymbolAddress(&p, g_h1);       h1   = (float*)p;
    cudaGetSymbolAddress(&p, g_Wh2);      Wh2  = (float*)p;
    cudaGetSymbolAddress(&p, g_h2t);      h2t  = (float*)p;
    cudaGetSymbolAddress(&p, g_P);        Pm   = (float*)p;
    cudaGetSymbolAddress(&p, g_Q);        Qm   = (float*)p;
    cudaGetSymbolAddress(&p, g_es1);      es1  = (float*)p;
    cudaGetSymbolAddress(&p, g_ed1);      ed1  = (float*)p;
    cudaGetSymbolAddress(&p, g_es2);      es2  = (float*)p;
    cudaGetSymbolAddress(&p, g_ed2);      ed2  = (float*)p;
    cudaGetSymbolAddress(&p, g_bnsum);    bnsum = (float*)p;
    cudaGetSymbolAddress(&p, g_bnss);     bnss  = (float*)p;
    cudaGetSymbolAddress(&p, g_scale);    scale = (float*)p;
    cudaGetSymbolAddress(&p, g_shift);    shift = (float*)p;
    cudaGetSymbolAddress(&p, g_pool);     pool  = (float*)p;
    cudaGetSymbolAddress(&p, g_cnt);      cnt   = (float*)p;
    cudaGetSymbolAddress(&p, g_src);      srcA  = (int*)p;
    cudaGetSymbolAddress(&p, g_dst);      dstA  = (int*)p;
    cudaGetSymbolAddress(&p, g_batch);    batchA = (int*)p;
    cudaGetSymbolAddress(&p, g_deg);      deg   = (int*)p;
    cudaGetSymbolAddress(&p, g_rowstart); rowstart = (int*)p;
    cudaGetSymbolAddress(&p, g_pos);      pos   = (int*)p;
    cudaGetSymbolAddress(&p, g_csr_src);  csrs  = (int*)p;
    cudaGetSymbolAddress(&p, g_csr_eid);  csre  = (int*)p;

    // ---- index prep + CSR by dst ----
    detect_kernel<<<1, 256>>>((const unsigned*)eidx, 4096);
    convert_idx_kernel<<<(2 * E + 255) / 256, 256>>>(eidx, srcA, dstA, E);
    convert_batch_kernel<<<(N + 255) / 256, 256>>>(batch, batchA, N);
    zero_kernel<<<(N + 255) / 256, 256>>>((float*)deg, (size_t)N);
    count_deg_kernel<<<(E + 255) / 256, 256>>>(dstA, deg, E);
    scan_kernel<<<1, 1024>>>(deg, rowstart, N);
    copy_int_kernel<<<(N + 255) / 256, 256>>>(rowstart, pos, N);
    fill_csr_kernel<<<(E + 255) / 256, 256>>>(srcA, dstA, pos, csrs, csre, E);

    // ---- layer 1 ----
    w1t_kernel<<<(IN_F * C1 + 255) / 256, 256>>>(W1, W1t);
    {
        dim3 g((N + 127) / 128, C1 / 128);
        sgemm_kernel<<<g, 256>>>(x, W1t, Wh1, N, C1, IN_F);
    }
    node_scores_kernel<<<(N * 32 + 255) / 256, 256>>>(Wh1, a_src1, a_dst1, es1, ed1, N, H1, HID);
    gat_aggregate_kernel<<<(N * H1 * 32 + 255) / 256, 256>>>(
        rowstart, csrs, csre, es1, ed1, Wh1, h1, nullptr, N, H1, HID);
    zero_kernel<<<2, 256>>>(bnsum, (size_t)C1);
    zero_kernel<<<2, 256>>>(bnss, (size_t)C1);
    elu_stats_kernel<<<256, C1>>>(h1, h1, bnsum, bnss, N, C1);
    bn_final_kernel<<<2, 256>>>(bnsum, bnss, bn1_g, bn1_b, scale, shift, C1, (float)N);
    bn_apply_kernel<<<(unsigned)(((size_t)N * C1 + 255) / 256), 256>>>(
        h1, h1, scale, shift, (size_t)N * C1, C1 - 1);

    // ---- layer 2 ----
    {
        dim3 g((N + 127) / 128, 1);
        sgemm_kernel<<<g, 256>>>(h1, W2, Wh2, N, HID, C1);
    }
    node_scores_kernel<<<(N * 32 + 255) / 256, 256>>>(Wh2, a_src2, a_dst2, es2, ed2, N, 1, HID);
    gat_aggregate_kernel<<<(N * 32 + 255) / 256, 256>>>(
        rowstart, csrs, csre, es2, ed2, Wh2, h2t, out_attn, N, 1, HID);
    zero_kernel<<<1, 256>>>(bnsum, (size_t)HID);
    zero_kernel<<<1, 256>>>(bnss, (size_t)HID);
    elu_stats_kernel<<<256, HID>>>(h2t, h2t, bnsum, bnss, N, HID);
    bn_final_kernel<<<1, 128>>>(bnsum, bnss, bn2_g, bn2_b, scale, shift, HID, (float)N);
    bn_apply_kernel<<<(unsigned)(((size_t)N * HID + 255) / 256), 256>>>(
        h2t, out_h2, scale, shift, (size_t)N * HID, HID - 1);

    // ---- pooling + classifier ----
    // BUGFIX (R4): pool has NUM_GRAPHS*HID = 2048 elements; previous launch
    // only zeroed the first 256, so atomicAdds accumulated across graph
    // replays (post-timing divergence on logits). Cover the full buffer.
    zero_kernel<<<(NUM_GRAPHS * HID + 255) / 256, 256>>>(pool, (size_t)(NUM_GRAPHS * HID));
    zero_kernel<<<1, 32>>>(cnt, (size_t)NUM_GRAPHS);
    pool_kernel<<<128, 128>>>(out_h2, batchA, N, pool, cnt);
    classifier_kernel<<<1, 1024>>>(pool, cnt, cls_w1, cls_b1, cls_w2, cls_b2, out_logits);

    // ---- edge importance: P = h2 @ W_top, Q = h2 @ W_bot ----
    {
        dim3 g((N + 127) / 128, 1);
        sgemm_kernel<<<g, 256>>>(out_h2, ep_w1, Pm, N, HID, HID);
        sgemm_kernel<<<g, 256>>>(out_h2, ep_w1 + HID * HID, Qm, N, HID, HID);
    }
    edge_imp_kernel<<<(unsigned)(((size_t)E * 32 + 255) / 256), 256>>>(
        srcA, dstA, Pm, Qm, ep_b1, ep_w2, ep_b2, out_imp, E);
}